// round 2
// baseline (speedup 1.0000x reference)
#include <cuda_runtime.h>
#include <math.h>

#define HD 512
#define WD 512
#define BD 32
#define NRING 257      // rings 0..256
#define NBINS 258      // +1 drop bin (r > 256)

// Scratch: row-FFT intermediate Fz[b][h][w] (complex). 64 MB static device array.
__device__ float2 g_fft[(size_t)BD * HD * WD];
// Ring accumulators: [r*BD+b] = {Cr,Ci,C1,C2}
__device__ float4 g_bins[NBINS * BD];
// Twiddle LUT: g_tw[j] = exp(-i*pi*j/256) = exp(-2*pi*i*j/512)
__device__ float2 g_tw[256];

__device__ __forceinline__ float2 cadd(float2 a, float2 b){ return make_float2(a.x+b.x, a.y+b.y); }
__device__ __forceinline__ float2 csub(float2 a, float2 b){ return make_float2(a.x-b.x, a.y-b.y); }
__device__ __forceinline__ float2 cmul(float2 a, float2 b){ return make_float2(a.x*b.x - a.y*b.y, a.x*b.y + a.y*b.x); }

// ---------------- init: twiddle table + zero bins ----------------
__global__ void init_tables() {
    int i = threadIdx.x;                     // 256 threads
    float s, c;
    sincospif(-(float)i / 256.0f, &s, &c);
    g_tw[i] = make_float2(c, s);
    float* gb = (float*)g_bins;
    for (int j = i; j < NBINS * BD * 4; j += 256) gb[j] = 0.0f;
}

// 512-point forward complex FFT, Stockham autosort, radix-2, 9 stages.
// Twiddles from shared LUT: tw[k<<shift] == exp(-i*pi*k/l), exact same values
// as the sincospif path. Returns buffer holding natural-order result.
__device__ float2* fft512(float2* x, float2* y, const float2* __restrict__ tw, int tid) {
    const int m = 256;
    int shift = 8;
    #pragma unroll
    for (int l = 1; l < 512; l <<= 1) {
        __syncthreads();
        #pragma unroll
        for (int q = 0; q < 2; q++) {
            int j = tid + q * 128;           // butterfly index 0..255
            int k = j & (l - 1);
            float2 w = tw[k << shift];
            float2 a = x[j];
            float2 b = cmul(w, x[j + m]);
            int idx = ((j - k) << 1) + k;
            y[idx]     = cadd(a, b);
            y[idx + l] = csub(a, b);
        }
        shift--;
        float2* t = x; x = y; y = t;
    }
    __syncthreads();
    return x;
}

// ---------------- Pass 1: row FFTs. One block per (b,h) row. ----------------
__global__ void __launch_bounds__(128) pass1_rows(const float* __restrict__ o,
                                                  const float* __restrict__ t) {
    __shared__ float2 bufA[512];
    __shared__ float2 bufB[512];
    __shared__ float2 tw[256];
    int row = blockIdx.x;                    // 0 .. BD*HD-1
    int tid = threadIdx.x;
    tw[tid]       = g_tw[tid];
    tw[tid + 128] = g_tw[tid + 128];
    const float* op = o + (size_t)row * WD;
    const float* tp = t + (size_t)row * WD;
    #pragma unroll
    for (int w = tid; w < 512; w += 128)
        bufA[w] = make_float2(op[w], tp[w]);          // z = o + i*t
    float2* res = fft512(bufA, bufB, tw, tid);
    float2* out = g_fft + (size_t)row * WD;
    #pragma unroll
    for (int w = tid; w < 512; w += 128)
        out[w] = res[w];
}

// ------- Pass 2: column-pair FFTs + ring binning. Block = (pair p, batch b). -------
__global__ void __launch_bounds__(128) pass2_cols() {
    __shared__ float2 A0[512];
    __shared__ float2 A1[512];
    __shared__ float2 B0[512];
    __shared__ float2 B1[512];
    __shared__ float2 tw[256];
    __shared__ float  sbin[4 * NBINS * 4];   // per-warp private copies

    int p  = blockIdx.x;                    // primary column 0..256
    int b  = blockIdx.y;
    int w2 = (512 - p) & 511;               // mirror column
    bool self = (w2 == p);                  // p == 0 or p == 256
    int tid = threadIdx.x;

    tw[tid]       = g_tw[tid];
    tw[tid + 128] = g_tw[tid + 128];
    for (int i = tid; i < 4 * NBINS * 4; i += 128) sbin[i] = 0.0f;

    const float2* base = g_fft + (size_t)b * HD * WD;
    for (int h = tid; h < 512; h += 128) {
        A0[h] = base[(size_t)h * WD + p];
        B0[h] = base[(size_t)h * WD + w2];
    }
    float2* FA = fft512(A0, A1, tw, tid);
    float2* FB = self ? FA : fft512(B0, B1, tw, tid);   // uniform over block

    int fw = (p <= 255) ? p : p - 512;      // signed frequency of column
    float fw2 = (float)(fw * fw);
    const float scale = 1.0f / (512.0f * 512.0f);   // norm='forward'
    float mulf = self ? 1.0f : 2.0f;
    float* mybin = &sbin[(tid >> 5) * (NBINS * 4)];

    for (int kh = tid; kh < 512; kh += 128) {
        float2 P  = FA[kh];                             // Fz(kh, p)
        int   khm = (512 - kh) & 511;
        float2 Mc = FB[khm];                            // Fz(-kh, -p)
        float px = P.x * scale,  py = P.y * scale;
        float mx = Mc.x * scale, my = -Mc.y * scale;    // M = conj(Fz(-k))
        // F1 = (P+M)/2 ; F2 = -i*(P-M)/2
        float f1x = 0.5f * (px + mx), f1y = 0.5f * (py + my);
        float dx  = 0.5f * (px - mx), dy  = 0.5f * (py - my);
        float f2x = dy, f2y = -dx;
        float av  = f1x * f2x + f1y * f2y;              // Re(F1 conj F2)
        float bv  = f1y * f2x - f1x * f2y;              // Im(F1 conj F2)
        float c1  = f1x * f1x + f1y * f1y;
        float c2  = f2x * f2x + f2y * f2y;

        int fh = (kh <= 255) ? kh : kh - 512;
        float rr = sqrtf((float)(fh * fh) + fw2);
        int r = (int)rintf(rr);                         // round-half-even == jnp.round
        if (r > 256) r = 257;                           // drop bin

        atomicAdd(&mybin[r * 4 + 0], mulf * av);
        if (self) atomicAdd(&mybin[r * 4 + 1], bv);     // pair blocks: +b/-b cancel
        atomicAdd(&mybin[r * 4 + 2], mulf * c1);
        atomicAdd(&mybin[r * 4 + 3], mulf * c2);
    }
    __syncthreads();

    float* gb = (float*)g_bins;
    for (int i = tid; i < NBINS * 4; i += 128) {
        float v = sbin[i] + sbin[i + NBINS * 4] + sbin[i + 2 * NBINS * 4] + sbin[i + 3 * NBINS * 4];
        if (v != 0.0f) {
            int r = i >> 2, c = i & 3;
            atomicAdd(&gb[(r * BD + b) * 4 + c], v);
        }
    }
}

// ---------------- final ----------------
__global__ void __launch_bounds__(512) final_reduce(float* __restrict__ out) {
    __shared__ float red[16];
    int tid = threadIdx.x;
    float acc = 0.0f;
    for (int i = tid; i < NRING * BD; i += 512) {   // i = r*BD + b, r < 257
        float4 s = g_bins[i];
        float frc = sqrtf(s.x * s.x + s.y * s.y) / (sqrtf(s.z * s.w) + 1e-8f);
        float d = 1.0f - frc;
        acc += d * d;
    }
    #pragma unroll
    for (int o = 16; o > 0; o >>= 1)
        acc += __shfl_xor_sync(0xffffffffu, acc, o);
    if ((tid & 31) == 0) red[tid >> 5] = acc;
    __syncthreads();
    if (tid < 32) {
        float v = (tid < 16) ? red[tid] : 0.0f;
        #pragma unroll
        for (int o = 8; o > 0; o >>= 1)
            v += __shfl_xor_sync(0xffffffffu, v, o);
        if (tid == 0) out[0] = v / (float)(NRING * BD);
    }
}

extern "C" void kernel_launch(void* const* d_in, const int* in_sizes, int n_in,
                              void* d_out, int out_size) {
    const float* o = (const float*)d_in[0];   // output  (32,1,512,512) f32
    const float* t = (const float*)d_in[1];   // target  (32,1,512,512) f32
    float* out = (float*)d_out;

    init_tables<<<1, 256>>>();
    pass1_rows<<<BD * HD, 128>>>(o, t);
    dim3 g2(NRING, BD);
    pass2_cols<<<g2, 128>>>();
    final_reduce<<<1, 512>>>(out);
}

// round 4
// speedup vs baseline: 1.1278x; 1.1278x over previous
#include <cuda_runtime.h>
#include <math.h>

#define HD 512
#define WD 512
#define BD 32
#define NRING 257      // rings 0..256
#define NBINS 258      // +1 drop bin (r > 256)

// Transposed row-FFT intermediate: g_fftT[b][w][h] (complex). 64 MB.
__device__ float2 g_fftT[(size_t)BD * WD * HD];
// Ring accumulators [r*BD+b] = {Cr,Ci,C1,C2}. Zero-initialized at module load,
// re-zeroed by final_reduce after reading -> every (re)play starts clean.
__device__ float4 g_bins[NBINS * BD];
// Twiddle LUT: g_tw[j] = exp(-i*pi*j/256)
__device__ float2 g_tw[256];

__device__ __forceinline__ float2 cadd(float2 a, float2 b){ return make_float2(a.x+b.x, a.y+b.y); }
__device__ __forceinline__ float2 csub(float2 a, float2 b){ return make_float2(a.x-b.x, a.y-b.y); }
__device__ __forceinline__ float2 cmul(float2 a, float2 b){ return make_float2(a.x*b.x - a.y*b.y, a.x*b.y + a.y*b.x); }

__global__ void init_tw() {
    int i = threadIdx.x;                     // 256 threads
    float s, c;
    sincospif(-(float)i / 256.0f, &s, &c);
    g_tw[i] = make_float2(c, s);
}

// 512-pt forward complex FFT, Stockham radix-2, 9 stages, 128 worker lanes
// (lt = 0..127). Called from 256-thread blocks: both halves must call with the
// same trip count (single call site). Result lands in the initial 'y' buffer.
__device__ void fft512(float2* x, float2* y, int lt) {
    const int m = 256;
    int shift = 8;
    #pragma unroll
    for (int l = 1; l < 512; l <<= 1) {
        __syncthreads();
        #pragma unroll
        for (int q = 0; q < 2; q++) {
            int j = lt + q * 128;            // butterfly index 0..255
            int k = j & (l - 1);
            float2 w = __ldg(&g_tw[k << shift]);
            float2 a = x[j];
            float2 b = cmul(w, x[j + m]);
            int idx = ((j - k) << 1) + k;
            y[idx]     = cadd(a, b);
            y[idx + l] = csub(a, b);
        }
        shift--;
        float2* t = x; x = y; y = t;
    }
    __syncthreads();
}

// ---- Pass 1: row FFTs, 2 rows/block, transposed store. ----
__global__ void __launch_bounds__(256) pass1_rows(const float* __restrict__ o,
                                                  const float* __restrict__ t) {
    __shared__ float2 X0[1024];
    __shared__ float2 X1[1024];
    int tid = threadIdx.x;
    int half = tid >> 7, lt = tid & 127;
    int rp = blockIdx.x;                     // 0 .. BD*HD/2-1
    int r0 = rp * 2;
    int b  = r0 >> 9;
    int h0 = r0 & 511;                       // even
    int r  = r0 + half;
    const float* op = o + (size_t)r * WD;
    const float* tp = t + (size_t)r * WD;
    int off = half * 512;
    #pragma unroll
    for (int w = lt; w < 512; w += 128)
        X0[off + w] = make_float2(op[w], tp[w]);     // z = o + i*t
    fft512(X0 + off, X1 + off, lt);                  // 9 stages -> result in X1
    // fft512 ends with __syncthreads(): both rows' results visible.
    float4* outp = (float4*)(g_fftT + (size_t)b * WD * HD);
    #pragma unroll
    for (int w = tid; w < 512; w += 256) {
        float2 v0 = X1[w];
        float2 v1 = X1[512 + w];
        outp[w * 256 + (h0 >> 1)] = make_float4(v0.x, v0.y, v1.x, v1.y);
    }
}

// ---- Pass 2: column-pair FFTs (coalesced loads) + ring binning. ----
__global__ void __launch_bounds__(256) pass2_cols() {
    __shared__ float2 A0[512];
    __shared__ float2 A1[512];
    __shared__ float2 B0[512];
    __shared__ float2 B1[512];
    __shared__ float  sbin[2 * NBINS * 4];

    int p  = blockIdx.x;                     // primary column 0..256
    int b  = blockIdx.y;
    int w2 = (512 - p) & 511;                // mirror column
    bool self = (w2 == p);                   // p == 0 or 256
    int tid = threadIdx.x;
    int half = tid >> 7, lt = tid & 127;

    for (int i = tid; i < 2 * NBINS * 4; i += 256) sbin[i] = 0.0f;

    const float2* base = g_fftT + (size_t)b * WD * HD;
    const float2* colA = base + (size_t)p  * HD;     // contiguous 4KB
    const float2* colB = base + (size_t)w2 * HD;
    for (int h = tid; h < 512; h += 256) {
        A0[h] = colA[h];
        B0[h] = colB[h];
    }
    // Two FFTs in parallel: warps 0-3 -> A, warps 4-7 -> B (single call site).
    float2* x = half ? B0 : A0;
    float2* y = half ? B1 : A1;
    fft512(x, y, lt);
    float2* FA = A1;                         // results in initial 'y' buffers
    float2* FB = B1;

    int fw = (p <= 255) ? p : p - 512;
    float fw2 = (float)(fw * fw);
    const float scale = 1.0f / (512.0f * 512.0f);    // norm='forward'
    float mulf = self ? 1.0f : 2.0f;
    float* mybin = sbin + half * (NBINS * 4);

    for (int kh = tid; kh < 512; kh += 256) {
        float2 P  = FA[kh];                          // Fz(kh, p)
        int   khm = (512 - kh) & 511;
        float2 Mc = FB[khm];                         // Fz(-kh, -p)
        float px = P.x * scale,  py = P.y * scale;
        float mx = Mc.x * scale, my = -Mc.y * scale; // conj
        float f1x = 0.5f * (px + mx), f1y = 0.5f * (py + my);
        float dx  = 0.5f * (px - mx), dy  = 0.5f * (py - my);
        float f2x = dy, f2y = -dx;
        float av  = f1x * f2x + f1y * f2y;
        float bv  = f1y * f2x - f1x * f2y;
        float c1  = f1x * f1x + f1y * f1y;
        float c2  = f2x * f2x + f2y * f2y;

        int fh = (kh <= 255) ? kh : kh - 512;
        float rr = sqrtf((float)(fh * fh) + fw2);
        int r = (int)rintf(rr);                      // round-half-even == jnp.round
        if (r > 256) r = 257;                        // drop bin

        atomicAdd(&mybin[r * 4 + 0], mulf * av);
        if (self) atomicAdd(&mybin[r * 4 + 1], bv);  // pair blocks: +b/-b cancel
        atomicAdd(&mybin[r * 4 + 2], mulf * c1);
        atomicAdd(&mybin[r * 4 + 3], mulf * c2);
    }
    __syncthreads();

    float* gb = (float*)g_bins;
    for (int i = tid; i < NBINS * 4; i += 256) {
        float v = sbin[i] + sbin[i + NBINS * 4];
        if (v != 0.0f) {
            int r = i >> 2, c = i & 3;
            atomicAdd(&gb[(r * BD + b) * 4 + c], v);
        }
    }
}

// ---- Final: frc + mean, then re-zero bins for the next graph replay. ----
__global__ void __launch_bounds__(1024) final_reduce(float* __restrict__ out) {
    __shared__ float red[32];
    int tid = threadIdx.x;
    float acc = 0.0f;
    for (int i = tid; i < NBINS * BD; i += 1024) {   // i = r*BD + b
        float4 s = g_bins[i];
        g_bins[i] = make_float4(0.f, 0.f, 0.f, 0.f);
        int r = i / BD;
        if (r < NRING) {
            float frc = sqrtf(s.x * s.x + s.y * s.y) / (sqrtf(s.z * s.w) + 1e-8f);
            float d = 1.0f - frc;
            acc += d * d;
        }
    }
    #pragma unroll
    for (int o = 16; o > 0; o >>= 1)
        acc += __shfl_xor_sync(0xffffffffu, acc, o);
    if ((tid & 31) == 0) red[tid >> 5] = acc;
    __syncthreads();
    if (tid < 32) {
        float v = red[tid];
        #pragma unroll
        for (int o = 16; o > 0; o >>= 1)
            v += __shfl_xor_sync(0xffffffffu, v, o);
        if (tid == 0) out[0] = v / (float)(NRING * BD);
    }
}

extern "C" void kernel_launch(void* const* d_in, const int* in_sizes, int n_in,
                              void* d_out, int out_size) {
    const float* o = (const float*)d_in[0];   // output (32,1,512,512) f32
    const float* t = (const float*)d_in[1];   // target (32,1,512,512) f32
    float* out = (float*)d_out;

    init_tw<<<1, 256>>>();
    pass1_rows<<<BD * HD / 2, 256>>>(o, t);
    dim3 g2(NRING, BD);
    pass2_cols<<<g2, 256>>>();
    final_reduce<<<1, 1024>>>(out);
}

// round 5
// speedup vs baseline: 1.6113x; 1.4287x over previous
#include <cuda_runtime.h>
#include <math.h>

#define HD 512
#define WD 512
#define BD 32
#define NRING 257      // rings 0..256
#define NBINS 258      // +1 drop bin (r > 256)

#define PIDX(i) ((i) + ((i) >> 3))   // padded smem index, stride-9 per 8

// Transposed row-FFT intermediate: g_fftT[b][w][h] (complex). 64 MB.
__device__ __align__(16) float2 g_fftT[(size_t)BD * WD * HD];
// Ring accumulators [r*BD+b] = {Cr,Ci,C1,C2}. Zero at load; final_reduce re-zeros.
__device__ float4 g_bins[NBINS * BD];
// Twiddle LUT: g_tw512[j] = exp(-2*pi*i*j/512)
__device__ float2 g_tw512[512];

__device__ __forceinline__ float2 cadd(float2 a, float2 b){ return make_float2(a.x+b.x, a.y+b.y); }
__device__ __forceinline__ float2 csub(float2 a, float2 b){ return make_float2(a.x-b.x, a.y-b.y); }
__device__ __forceinline__ float2 cmul(float2 a, float2 b){ return make_float2(a.x*b.x - a.y*b.y, a.x*b.y + a.y*b.x); }

__global__ void init_tw() {
    int i = threadIdx.x;                     // 512 threads
    float s, c;
    sincospif(-(float)i / 256.0f, &s, &c);
    g_tw512[i] = make_float2(c, s);
}

// 8-point DFT, forward. b[u] = sum_i a[i] * exp(-2*pi*i*u*i/8)
__device__ __forceinline__ void dft8(const float2 a[8], float2 b[8]) {
    // even DFT4 of (a0,a2,a4,a6)
    float2 t0 = cadd(a[0], a[4]), t1 = csub(a[0], a[4]);
    float2 t2 = cadd(a[2], a[6]), t3 = csub(a[2], a[6]);
    float2 E0 = cadd(t0, t2), E2 = csub(t0, t2);
    float2 E1 = make_float2(t1.x + t3.y, t1.y - t3.x);   // t1 - i*t3
    float2 E3 = make_float2(t1.x - t3.y, t1.y + t3.x);   // t1 + i*t3
    // odd DFT4 of (a1,a3,a5,a7)
    float2 s0 = cadd(a[1], a[5]), s1 = csub(a[1], a[5]);
    float2 s2 = cadd(a[3], a[7]), s3 = csub(a[3], a[7]);
    float2 O0 = cadd(s0, s2), O2 = csub(s0, s2);
    float2 O1 = make_float2(s1.x + s3.y, s1.y - s3.x);
    float2 O3 = make_float2(s1.x - s3.y, s1.y + s3.x);
    const float r = 0.70710678118654752440f;
    float2 W1 = make_float2(r * (O1.x + O1.y), r * (O1.y - O1.x));   // w8^1 * O1
    float2 W2 = make_float2(O2.y, -O2.x);                            // -i * O2
    float2 W3 = make_float2(r * (O3.y - O3.x), -r * (O3.x + O3.y));  // w8^3 * O3
    b[0] = cadd(E0, O0); b[4] = csub(E0, O0);
    b[1] = cadd(E1, W1); b[5] = csub(E1, W1);
    b[2] = cadd(E2, W2); b[6] = csub(E2, W2);
    b[3] = cadd(E3, W3); b[7] = csub(E3, W3);
}

// ---- Pass 1: row FFTs (radix-8, 3 passes), 4 rows/block, transposed store. ----
__global__ void __launch_bounds__(256) pass1_rows(const float* __restrict__ o,
                                                  const float* __restrict__ t) {
    __shared__ float2 buf[4][576];
    __shared__ float2 sTwB[64];     // [(i-1)*8 + k]  = exp(-2pi*i*k/64)
    __shared__ float2 sTwC[448];    // [(i-1)*64 + j] = exp(-2pi*i*j/512)
    int tid = threadIdx.x;
    int f = tid >> 6, j = tid & 63;

    for (int m = tid; m < 56; m += 256) {
        int i = (m >> 3) + 1, k = m & 7;
        sTwB[m] = g_tw512[8 * i * k];
    }
    for (int m = tid; m < 448; m += 256) {
        int i = (m >> 6) + 1, jj = m & 63;
        sTwC[m] = g_tw512[i * jj];
    }

    int bx = blockIdx.x;
    int b  = bx >> 7;
    int r0 = (bx & 127) << 2;
    int gr = (b << 9) + r0 + f;
    const float* op = o + (size_t)gr * WD;
    const float* tp = t + (size_t)gr * WD;

    float2 v[8], w[8];
    #pragma unroll
    for (int i = 0; i < 8; i++)
        v[i] = make_float2(op[j + 64 * i], tp[j + 64 * i]);   // z = o + i*t

    // pass A (l=1, twiddles = 1)
    dft8(v, w);
    #pragma unroll
    for (int u = 0; u < 8; u++) buf[f][PIDX(8 * j + u)] = w[u];
    __syncthreads();
    // pass B (l=8)
    int k = j & 7;
    #pragma unroll
    for (int i = 0; i < 8; i++) v[i] = buf[f][PIDX(j + 64 * i)];
    #pragma unroll
    for (int i = 1; i < 8; i++) v[i] = cmul(v[i], sTwB[(i - 1) * 8 + k]);
    dft8(v, w);
    __syncthreads();
    {
        int base = (j & ~7) * 8 + k;
        #pragma unroll
        for (int u = 0; u < 8; u++) buf[f][PIDX(base + 8 * u)] = w[u];
    }
    __syncthreads();
    // pass C (l=64): output element j + 64u lands in w[u]
    #pragma unroll
    for (int i = 0; i < 8; i++) v[i] = buf[f][PIDX(j + 64 * i)];
    #pragma unroll
    for (int i = 1; i < 8; i++) v[i] = cmul(v[i], sTwC[(i - 1) * 64 + j]);
    dft8(v, w);
    __syncthreads();
    #pragma unroll
    for (int u = 0; u < 8; u++) buf[f][PIDX(j + 64 * u)] = w[u];
    __syncthreads();

    // transposed store: for each w, rows r0..r0+3 contiguous -> 2x float4 (32B)
    float4* outp = (float4*)(g_fftT + (size_t)b * WD * HD);
    #pragma unroll
    for (int q = 0; q < 2; q++) {
        int wv = tid + 256 * q;
        float2 q0 = buf[0][PIDX(wv)], q1 = buf[1][PIDX(wv)];
        float2 q2 = buf[2][PIDX(wv)], q3 = buf[3][PIDX(wv)];
        size_t i4 = ((size_t)wv * HD + r0) >> 1;
        outp[i4]     = make_float4(q0.x, q0.y, q1.x, q1.y);
        outp[i4 + 1] = make_float4(q2.x, q2.y, q3.x, q3.y);
    }
}

// ---- Pass 2: column-pair FFTs (radix-8) + ring binning. ----
__global__ void __launch_bounds__(128) pass2_cols() {
    __shared__ float2 buf[2][576];
    __shared__ float2 sTwB[64];
    __shared__ float2 sTwC[448];
    __shared__ float  sbin[2 * NBINS * 4];

    int tid = threadIdx.x;
    int half = tid >> 6, j = tid & 63;
    int p = blockIdx.x, b = blockIdx.y;
    int w2 = (512 - p) & 511;
    bool self = (w2 == p);

    for (int m = tid; m < 56; m += 128) {
        int i = (m >> 3) + 1, k = m & 7;
        sTwB[m] = g_tw512[8 * i * k];
    }
    for (int m = tid; m < 448; m += 128) {
        int i = (m >> 6) + 1, jj = m & 63;
        sTwC[m] = g_tw512[i * jj];
    }
    for (int m = tid; m < 2 * NBINS * 4; m += 128) sbin[m] = 0.0f;

    int col = half ? w2 : p;
    const float2* cp = g_fftT + ((size_t)b * WD + col) * HD;   // contiguous 4KB

    float2 v[8], w[8];
    #pragma unroll
    for (int i = 0; i < 8; i++) v[i] = cp[j + 64 * i];

    // pass A
    dft8(v, w);
    #pragma unroll
    for (int u = 0; u < 8; u++) buf[half][PIDX(8 * j + u)] = w[u];
    __syncthreads();
    // pass B
    int k = j & 7;
    #pragma unroll
    for (int i = 0; i < 8; i++) v[i] = buf[half][PIDX(j + 64 * i)];
    #pragma unroll
    for (int i = 1; i < 8; i++) v[i] = cmul(v[i], sTwB[(i - 1) * 8 + k]);
    dft8(v, w);
    __syncthreads();
    {
        int base = (j & ~7) * 8 + k;
        #pragma unroll
        for (int u = 0; u < 8; u++) buf[half][PIDX(base + 8 * u)] = w[u];
    }
    __syncthreads();
    // pass C
    #pragma unroll
    for (int i = 0; i < 8; i++) v[i] = buf[half][PIDX(j + 64 * i)];
    #pragma unroll
    for (int i = 1; i < 8; i++) v[i] = cmul(v[i], sTwC[(i - 1) * 64 + j]);
    dft8(v, w);
    __syncthreads();
    #pragma unroll
    for (int u = 0; u < 8; u++) buf[half][PIDX(j + 64 * u)] = w[u];
    __syncthreads();

    // ---- ring binning: FA = buf[0] (col p), FB = buf[1] (col w2) ----
    int fw = (p <= 255) ? p : p - 512;
    float fw2 = (float)(fw * fw);
    const float scale = 1.0f / (512.0f * 512.0f);   // norm='forward'
    float mulf = self ? 1.0f : 2.0f;
    float* mybin = sbin + half * (NBINS * 4);

    #pragma unroll
    for (int q = 0; q < 4; q++) {
        int kh  = tid + 128 * q;
        int khm = (512 - kh) & 511;
        float2 P  = buf[0][PIDX(kh)];                 // Fz(kh, p)
        float2 Mc = buf[1][PIDX(khm)];                // Fz(-kh, -p)
        float px = P.x * scale,  py = P.y * scale;
        float mx = Mc.x * scale, my = -Mc.y * scale;  // conj
        float f1x = 0.5f * (px + mx), f1y = 0.5f * (py + my);
        float dx  = 0.5f * (px - mx), dy  = 0.5f * (py - my);
        float f2x = dy, f2y = -dx;
        float av  = f1x * f2x + f1y * f2y;
        float bv  = f1y * f2x - f1x * f2y;
        float c1  = f1x * f1x + f1y * f1y;
        float c2  = f2x * f2x + f2y * f2y;

        int fh = (kh <= 255) ? kh : kh - 512;
        float rr = sqrtf((float)(fh * fh) + fw2);
        int r = (int)rintf(rr);                       // round-half-even == jnp.round
        if (r > 256) r = 257;                         // drop bin

        atomicAdd(&mybin[r * 4 + 0], mulf * av);
        if (self) atomicAdd(&mybin[r * 4 + 1], bv);   // pair blocks: +b/-b cancel
        atomicAdd(&mybin[r * 4 + 2], mulf * c1);
        atomicAdd(&mybin[r * 4 + 3], mulf * c2);
    }
    __syncthreads();

    float* gb = (float*)g_bins;
    for (int i = tid; i < NBINS * 4; i += 128) {
        float v2 = sbin[i] + sbin[i + NBINS * 4];
        if (v2 != 0.0f) {
            int r = i >> 2, c = i & 3;
            atomicAdd(&gb[(r * BD + b) * 4 + c], v2);
        }
    }
}

// ---- Final: frc + mean, then re-zero bins for the next graph replay. ----
__global__ void __launch_bounds__(1024) final_reduce(float* __restrict__ out) {
    __shared__ float red[32];
    int tid = threadIdx.x;
    float acc = 0.0f;
    for (int i = tid; i < NBINS * BD; i += 1024) {   // i = r*BD + b
        float4 s = g_bins[i];
        g_bins[i] = make_float4(0.f, 0.f, 0.f, 0.f);
        int r = i / BD;
        if (r < NRING) {
            float frc = sqrtf(s.x * s.x + s.y * s.y) / (sqrtf(s.z * s.w) + 1e-8f);
            float d = 1.0f - frc;
            acc += d * d;
        }
    }
    #pragma unroll
    for (int o = 16; o > 0; o >>= 1)
        acc += __shfl_xor_sync(0xffffffffu, acc, o);
    if ((tid & 31) == 0) red[tid >> 5] = acc;
    __syncthreads();
    if (tid < 32) {
        float v = red[tid];
        #pragma unroll
        for (int o = 16; o > 0; o >>= 1)
            v += __shfl_xor_sync(0xffffffffu, v, o);
        if (tid == 0) out[0] = v / (float)(NRING * BD);
    }
}

extern "C" void kernel_launch(void* const* d_in, const int* in_sizes, int n_in,
                              void* d_out, int out_size) {
    const float* o = (const float*)d_in[0];   // output (32,1,512,512) f32
    const float* t = (const float*)d_in[1];   // target (32,1,512,512) f32
    float* out = (float*)d_out;

    init_tw<<<1, 512>>>();
    pass1_rows<<<BD * HD / 4, 256>>>(o, t);
    dim3 g2(NRING, BD);
    pass2_cols<<<g2, 128>>>();
    final_reduce<<<1, 1024>>>(out);
}

// round 11
// speedup vs baseline: 2.0638x; 1.2808x over previous
#include <cuda_runtime.h>
#include <math.h>

#define HD 512
#define WD 512
#define BD 32
#define NRING 257      // rings 0..256
#define NBINS 258      // +1 drop bin (r > 256)
#define P2_BLOCKS_X 65 // ceil(257/4)
#define P2_NBLOCKS (P2_BLOCKS_X * BD)

#define PIDX(i) ((i) + ((i) >> 3))   // padded smem index, stride-9 per 8

// Transposed row-FFT intermediate: g_fftT[b][w][h] (complex). 64 MB.
__device__ __align__(16) float2 g_fftT[(size_t)BD * WD * HD];
// Ring accumulators [r*BD+b] = {Cr,Ci,C1,C2}. Zero at load; last pass2 block re-zeros.
__device__ float4 g_bins[NBINS * BD];
// Twiddle LUT: g_tw512[j] = exp(-2*pi*i*j/512)
__device__ float2 g_tw512[512];
// completion counter for fused finalization (reset each run by last block)
__device__ unsigned g_done;

__device__ __forceinline__ float2 cadd(float2 a, float2 b){ return make_float2(a.x+b.x, a.y+b.y); }
__device__ __forceinline__ float2 csub(float2 a, float2 b){ return make_float2(a.x-b.x, a.y-b.y); }
__device__ __forceinline__ float2 cmul(float2 a, float2 b){ return make_float2(a.x*b.x - a.y*b.y, a.x*b.y + a.y*b.x); }

__global__ void init_tw() {
    int i = threadIdx.x;                     // 512 threads
    float s, c;
    sincospif(-(float)i / 256.0f, &s, &c);
    g_tw512[i] = make_float2(c, s);
}

// 8-point DFT, forward.
__device__ __forceinline__ void dft8(const float2 a[8], float2 b[8]) {
    float2 t0 = cadd(a[0], a[4]), t1 = csub(a[0], a[4]);
    float2 t2 = cadd(a[2], a[6]), t3 = csub(a[2], a[6]);
    float2 E0 = cadd(t0, t2), E2 = csub(t0, t2);
    float2 E1 = make_float2(t1.x + t3.y, t1.y - t3.x);
    float2 E3 = make_float2(t1.x - t3.y, t1.y + t3.x);
    float2 s0 = cadd(a[1], a[5]), s1 = csub(a[1], a[5]);
    float2 s2 = cadd(a[3], a[7]), s3 = csub(a[3], a[7]);
    float2 O0 = cadd(s0, s2), O2 = csub(s0, s2);
    float2 O1 = make_float2(s1.x + s3.y, s1.y - s3.x);
    float2 O3 = make_float2(s1.x - s3.y, s1.y + s3.x);
    const float r = 0.70710678118654752440f;
    float2 W1 = make_float2(r * (O1.x + O1.y), r * (O1.y - O1.x));
    float2 W2 = make_float2(O2.y, -O2.x);
    float2 W3 = make_float2(r * (O3.y - O3.x), -r * (O3.x + O3.y));
    b[0] = cadd(E0, O0); b[4] = csub(E0, O0);
    b[1] = cadd(E1, W1); b[5] = csub(E1, W1);
    b[2] = cadd(E2, W2); b[6] = csub(E2, W2);
    b[3] = cadd(E3, W3); b[7] = csub(E3, W3);
}

// ---- Pass 1: row FFTs (radix-8, 3 passes), 4 rows/block, transposed store. ----
__global__ void __launch_bounds__(256) pass1_rows(const float* __restrict__ o,
                                                  const float* __restrict__ t) {
    __shared__ float2 buf[4][576];
    __shared__ float2 sTwB[64];
    __shared__ float2 sTwC[448];
    int tid = threadIdx.x;
    int f = tid >> 6, j = tid & 63;

    for (int m = tid; m < 56; m += 256) {
        int i = (m >> 3) + 1, k = m & 7;
        sTwB[m] = g_tw512[8 * i * k];
    }
    for (int m = tid; m < 448; m += 256) {
        int i = (m >> 6) + 1, jj = m & 63;
        sTwC[m] = g_tw512[i * jj];
    }

    int bx = blockIdx.x;
    int b  = bx >> 7;
    int r0 = (bx & 127) << 2;
    int gr = (b << 9) + r0 + f;
    const float* op = o + (size_t)gr * WD;
    const float* tp = t + (size_t)gr * WD;

    float2 v[8], w[8];
    #pragma unroll
    for (int i = 0; i < 8; i++)
        v[i] = make_float2(op[j + 64 * i], tp[j + 64 * i]);   // z = o + i*t

    dft8(v, w);                                               // pass A
    #pragma unroll
    for (int u = 0; u < 8; u++) buf[f][PIDX(8 * j + u)] = w[u];
    __syncthreads();
    int k = j & 7;                                            // pass B
    #pragma unroll
    for (int i = 0; i < 8; i++) v[i] = buf[f][PIDX(j + 64 * i)];
    #pragma unroll
    for (int i = 1; i < 8; i++) v[i] = cmul(v[i], sTwB[(i - 1) * 8 + k]);
    dft8(v, w);
    __syncthreads();
    {
        int base = (j & ~7) * 8 + k;
        #pragma unroll
        for (int u = 0; u < 8; u++) buf[f][PIDX(base + 8 * u)] = w[u];
    }
    __syncthreads();
    #pragma unroll
    for (int i = 0; i < 8; i++) v[i] = buf[f][PIDX(j + 64 * i)];   // pass C
    #pragma unroll
    for (int i = 1; i < 8; i++) v[i] = cmul(v[i], sTwC[(i - 1) * 64 + j]);
    dft8(v, w);
    __syncthreads();
    #pragma unroll
    for (int u = 0; u < 8; u++) buf[f][PIDX(j + 64 * u)] = w[u];
    __syncthreads();

    float4* outp = (float4*)(g_fftT + (size_t)b * WD * HD);
    #pragma unroll
    for (int q = 0; q < 2; q++) {
        int wv = tid + 256 * q;
        float2 q0 = buf[0][PIDX(wv)], q1 = buf[1][PIDX(wv)];
        float2 q2 = buf[2][PIDX(wv)], q3 = buf[3][PIDX(wv)];
        size_t i4 = ((size_t)wv * HD + r0) >> 1;
        outp[i4]     = make_float4(q0.x, q0.y, q1.x, q1.y);
        outp[i4 + 1] = make_float4(q2.x, q2.y, q3.x, q3.y);
    }
}

// ---- Pass 2: 4 column-pairs per block, FFTs + segmented ring binning + fused final. ----
__global__ void __launch_bounds__(128) pass2_cols(float* __restrict__ out) {
    __shared__ float2 buf[2][576];
    __shared__ float2 sTwB[64];
    __shared__ float2 sTwC[448];
    __shared__ float  sbin[NBINS * 4];
    __shared__ unsigned sIsLast;

    int tid = threadIdx.x;
    int half = tid >> 6, j = tid & 63;
    int b = blockIdx.y;
    unsigned lane = tid & 31;
    const unsigned full = 0xffffffffu;

    for (int m = tid; m < 56; m += 128) {
        int i = (m >> 3) + 1, k = m & 7;
        sTwB[m] = g_tw512[8 * i * k];
    }
    for (int m = tid; m < 448; m += 128) {
        int i = (m >> 6) + 1, jj = m & 63;
        sTwC[m] = g_tw512[i * jj];
    }
    for (int m = tid; m < NBINS * 4; m += 128) sbin[m] = 0.0f;

    #pragma unroll 1
    for (int pi = 0; pi < 4; pi++) {
        int p = blockIdx.x * 4 + pi;
        if (p < NRING) {                         // uniform over block
            int w2 = (512 - p) & 511;
            bool self = (w2 == p);
            int col = half ? w2 : p;
            const float2* cp = g_fftT + ((size_t)b * WD + col) * HD;

            float2 v[8], w[8];
            __syncthreads();                      // buffers free from prev pair
            #pragma unroll
            for (int i = 0; i < 8; i++) v[i] = cp[j + 64 * i];

            dft8(v, w);                           // pass A
            #pragma unroll
            for (int u = 0; u < 8; u++) buf[half][PIDX(8 * j + u)] = w[u];
            __syncthreads();
            int k = j & 7;                        // pass B
            #pragma unroll
            for (int i = 0; i < 8; i++) v[i] = buf[half][PIDX(j + 64 * i)];
            #pragma unroll
            for (int i = 1; i < 8; i++) v[i] = cmul(v[i], sTwB[(i - 1) * 8 + k]);
            dft8(v, w);
            __syncthreads();
            {
                int base = (j & ~7) * 8 + k;
                #pragma unroll
                for (int u = 0; u < 8; u++) buf[half][PIDX(base + 8 * u)] = w[u];
            }
            __syncthreads();
            #pragma unroll
            for (int i = 0; i < 8; i++) v[i] = buf[half][PIDX(j + 64 * i)];  // pass C
            #pragma unroll
            for (int i = 1; i < 8; i++) v[i] = cmul(v[i], sTwC[(i - 1) * 64 + j]);
            dft8(v, w);
            __syncthreads();
            #pragma unroll
            for (int u = 0; u < 8; u++) buf[half][PIDX(j + 64 * u)] = w[u];
            __syncthreads();

            // ---- binning: FA = buf[0] (col p), FB = buf[1] (col w2) ----
            int fw = (p <= 255) ? p : p - 512;
            float fw2 = (float)(fw * fw);
            const float scale = 1.0f / (512.0f * 512.0f);
            float mulf = self ? 1.0f : 2.0f;

            #pragma unroll
            for (int q = 0; q < 4; q++) {
                int kh  = tid + 128 * q;
                int khm = (512 - kh) & 511;
                float2 P  = buf[0][PIDX(kh)];
                float2 Mc = buf[1][PIDX(khm)];
                float px = P.x * scale,  py = P.y * scale;
                float mx = Mc.x * scale, my = -Mc.y * scale;
                float f1x = 0.5f * (px + mx), f1y = 0.5f * (py + my);
                float dx  = 0.5f * (px - mx), dy  = 0.5f * (py - my);
                float f2x = dy, f2y = -dx;
                float av  = mulf * (f1x * f2x + f1y * f2y);
                float c1  = mulf * (f1x * f1x + f1y * f1y);
                float c2  = mulf * (f2x * f2x + f2y * f2y);

                int fh = (kh <= 255) ? kh : kh - 512;
                float rr = sqrtf((float)(fh * fh) + fw2);
                int r = (int)rintf(rr);           // round-half-even == jnp.round
                if (r > 256) r = 257;

                // warp-segmented sums: one atomic per contiguous equal-r run
                int rup = __shfl_up_sync(full, r, 1);
                bool head = (lane == 0) || (rup != r);
                unsigned hm = __ballot_sync(full, head);
                unsigned below = hm & (full >> (31 - lane));
                int myhead = 31 - __clz(below);
                bool tail = (lane == 31) || ((hm >> (lane + 1)) & 1u);
                int src = (myhead > 0) ? myhead - 1 : 0;

                float s0 = av, s1 = c1, s2 = c2;
                #pragma unroll
                for (int o = 1; o < 32; o <<= 1) {
                    float u0 = __shfl_up_sync(full, s0, o);
                    float u1 = __shfl_up_sync(full, s1, o);
                    float u2 = __shfl_up_sync(full, s2, o);
                    if (lane >= (unsigned)o) { s0 += u0; s1 += u1; s2 += u2; }
                }
                float b0 = __shfl_sync(full, s0, src);
                float b1 = __shfl_sync(full, s1, src);
                float b2 = __shfl_sync(full, s2, src);
                if (myhead == 0) { b0 = 0.f; b1 = 0.f; b2 = 0.f; }
                if (tail) {
                    atomicAdd(&sbin[r * 4 + 0], s0 - b0);
                    atomicAdd(&sbin[r * 4 + 2], s1 - b1);
                    atomicAdd(&sbin[r * 4 + 3], s2 - b2);
                }
                if (self) {
                    float bv = f1y * f2x - f1x * f2y;
                    atomicAdd(&sbin[r * 4 + 1], bv);   // pair blocks: +b/-b cancel
                }
            }
            __syncthreads();
        }
    }

    // ---- flush accumulated bins (4 pairs) to global ----
    float* gb = (float*)g_bins;
    for (int i = tid; i < NBINS * 4; i += 128) {
        float v2 = sbin[i];
        if (v2 != 0.0f) {
            int r = i >> 2, c = i & 3;
            atomicAdd(&gb[(r * BD + b) * 4 + c], v2);
        }
    }
    __syncthreads();

    // ---- last block finalizes: frc + mean, re-zero bins & counter ----
    if (tid == 0) {
        __threadfence();
        unsigned v = atomicAdd(&g_done, 1u);
        sIsLast = (v == (unsigned)(P2_NBLOCKS - 1));
    }
    __syncthreads();
    if (sIsLast) {
        float acc = 0.0f;
        const float4 zero4 = make_float4(0.f, 0.f, 0.f, 0.f);
        for (int i = tid; i < NBINS * BD; i += 128) {
            float4 s = __ldcg(&g_bins[i]);
            __stcg(&g_bins[i], zero4);
            int r = i / BD;
            if (r < NRING) {
                float frc = sqrtf(s.x * s.x + s.y * s.y) / (sqrtf(s.z * s.w) + 1e-8f);
                float d = 1.0f - frc;
                acc += d * d;
            }
        }
        #pragma unroll
        for (int o = 16; o > 0; o >>= 1)
            acc += __shfl_xor_sync(full, acc, o);
        __shared__ float red[4];
        if (lane == 0) red[tid >> 5] = acc;
        __syncthreads();
        if (tid == 0) {
            out[0] = (red[0] + red[1] + red[2] + red[3]) / (float)(NRING * BD);
            atomicExch(&g_done, 0u);
        }
    }
}

extern "C" void kernel_launch(void* const* d_in, const int* in_sizes, int n_in,
                              void* d_out, int out_size) {
    const float* o = (const float*)d_in[0];   // output (32,1,512,512) f32
    const float* t = (const float*)d_in[1];   // target (32,1,512,512) f32
    float* out = (float*)d_out;

    init_tw<<<1, 512>>>();
    pass1_rows<<<BD * HD / 4, 256>>>(o, t);
    dim3 g2(P2_BLOCKS_X, BD);
    pass2_cols<<<g2, 128>>>(out);
}

// round 14
// speedup vs baseline: 2.1899x; 1.0611x over previous
#include <cuda_runtime.h>
#include <math.h>

#define HD 512
#define WD 512
#define BD 32
#define NRING 257      // rings 0..256
#define NBINS 258      // +1 drop bin (r > 256)
#define P2_BLOCKS_X 65 // ceil(257/4)
#define P2_NBLOCKS (P2_BLOCKS_X * BD)

#define PIDX(i) ((i) + ((i) >> 3))   // padded smem index, stride-9 per 8

// Transposed row-FFT intermediate: g_fftT[b][w][h] (complex). 64 MB.
__device__ __align__(16) float2 g_fftT[(size_t)BD * WD * HD];
// Ring accumulators [r*BD+b] = {Cr,Ci,C1,C2}. Zero at load; last pass2 block re-zeros.
__device__ float4 g_bins[NBINS * BD];
// completion counter for fused finalization (reset each run by last block)
__device__ unsigned g_done;

__device__ __forceinline__ float2 cadd(float2 a, float2 b){ return make_float2(a.x+b.x, a.y+b.y); }
__device__ __forceinline__ float2 csub(float2 a, float2 b){ return make_float2(a.x-b.x, a.y-b.y); }
__device__ __forceinline__ float2 cmul(float2 a, float2 b){ return make_float2(a.x*b.x - a.y*b.y, a.x*b.y + a.y*b.x); }

// twiddle: exp(-2*pi*i*idx/512), idx in [0,512)
__device__ __forceinline__ float2 twd(int idx) {
    float s, c;
    sincospif(-(float)idx / 256.0f, &s, &c);
    return make_float2(c, s);
}

// 8-point DFT, forward.
__device__ __forceinline__ void dft8(const float2 a[8], float2 b[8]) {
    float2 t0 = cadd(a[0], a[4]), t1 = csub(a[0], a[4]);
    float2 t2 = cadd(a[2], a[6]), t3 = csub(a[2], a[6]);
    float2 E0 = cadd(t0, t2), E2 = csub(t0, t2);
    float2 E1 = make_float2(t1.x + t3.y, t1.y - t3.x);
    float2 E3 = make_float2(t1.x - t3.y, t1.y + t3.x);
    float2 s0 = cadd(a[1], a[5]), s1 = csub(a[1], a[5]);
    float2 s2 = cadd(a[3], a[7]), s3 = csub(a[3], a[7]);
    float2 O0 = cadd(s0, s2), O2 = csub(s0, s2);
    float2 O1 = make_float2(s1.x + s3.y, s1.y - s3.x);
    float2 O3 = make_float2(s1.x - s3.y, s1.y + s3.x);
    const float r = 0.70710678118654752440f;
    float2 W1 = make_float2(r * (O1.x + O1.y), r * (O1.y - O1.x));
    float2 W2 = make_float2(O2.y, -O2.x);
    float2 W3 = make_float2(r * (O3.y - O3.x), -r * (O3.x + O3.y));
    b[0] = cadd(E0, O0); b[4] = csub(E0, O0);
    b[1] = cadd(E1, W1); b[5] = csub(E1, W1);
    b[2] = cadd(E2, W2); b[6] = csub(E2, W2);
    b[3] = cadd(E3, W3); b[7] = csub(E3, W3);
}

// ---- Pass 1: row FFTs (radix-8, 3 passes), 4 rows/block, transposed store. ----
__global__ void __launch_bounds__(256) pass1_rows(const float* __restrict__ o,
                                                  const float* __restrict__ t) {
    __shared__ float2 buf[4][576];
    __shared__ float2 sTwB[64];
    __shared__ float2 sTwC[448];
    int tid = threadIdx.x;
    int f = tid >> 6, j = tid & 63;

    for (int m = tid; m < 56; m += 256) {
        int i = (m >> 3) + 1, k = m & 7;
        sTwB[m] = twd(8 * i * k);
    }
    for (int m = tid; m < 448; m += 256) {
        int i = (m >> 6) + 1, jj = m & 63;
        sTwC[m] = twd(i * jj);
    }

    int bx = blockIdx.x;
    int b  = bx >> 7;
    int r0 = (bx & 127) << 2;
    int gr = (b << 9) + r0 + f;
    const float* op = o + (size_t)gr * WD;
    const float* tp = t + (size_t)gr * WD;

    float2 v[8], w[8];
    #pragma unroll
    for (int i = 0; i < 8; i++)
        v[i] = make_float2(op[j + 64 * i], tp[j + 64 * i]);   // z = o + i*t

    dft8(v, w);                                               // pass A
    __syncthreads();                                          // tw tables ready
    #pragma unroll
    for (int u = 0; u < 8; u++) buf[f][PIDX(8 * j + u)] = w[u];
    __syncthreads();
    int k = j & 7;                                            // pass B
    #pragma unroll
    for (int i = 0; i < 8; i++) v[i] = buf[f][PIDX(j + 64 * i)];
    #pragma unroll
    for (int i = 1; i < 8; i++) v[i] = cmul(v[i], sTwB[(i - 1) * 8 + k]);
    dft8(v, w);
    __syncthreads();
    {
        int base = (j & ~7) * 8 + k;
        #pragma unroll
        for (int u = 0; u < 8; u++) buf[f][PIDX(base + 8 * u)] = w[u];
    }
    __syncthreads();
    #pragma unroll
    for (int i = 0; i < 8; i++) v[i] = buf[f][PIDX(j + 64 * i)];   // pass C
    #pragma unroll
    for (int i = 1; i < 8; i++) v[i] = cmul(v[i], sTwC[(i - 1) * 64 + j]);
    dft8(v, w);
    __syncthreads();
    #pragma unroll
    for (int u = 0; u < 8; u++) buf[f][PIDX(j + 64 * u)] = w[u];
    __syncthreads();

    float4* outp = (float4*)(g_fftT + (size_t)b * WD * HD);
    #pragma unroll
    for (int q = 0; q < 2; q++) {
        int wv = tid + 256 * q;
        float2 q0 = buf[0][PIDX(wv)], q1 = buf[1][PIDX(wv)];
        float2 q2 = buf[2][PIDX(wv)], q3 = buf[3][PIDX(wv)];
        size_t i4 = ((size_t)wv * HD + r0) >> 1;
        outp[i4]     = make_float4(q0.x, q0.y, q1.x, q1.y);
        outp[i4 + 1] = make_float4(q2.x, q2.y, q3.x, q3.y);
    }
}

// ---- Pass 2: 256 threads, 2 pairs concurrent x 2 iters, segmented binning, fused final. ----
__global__ void __launch_bounds__(256) pass2_cols(float* __restrict__ out) {
    __shared__ float2 buf[4][576];
    __shared__ float2 sTwB[64];
    __shared__ float2 sTwC[448];
    __shared__ float  sbin[NBINS * 4];
    __shared__ unsigned sIsLast;

    int tid = threadIdx.x;
    int quarter = tid >> 6;          // 0..3: FFT unit
    int pairq   = tid >> 7;          // 0: pair A, 1: pair B
    int half    = quarter & 1;       // column within pair
    int j = tid & 63;
    int b = blockIdx.y;
    unsigned lane = tid & 31;
    const unsigned full = 0xffffffffu;

    for (int m = tid; m < 56; m += 256) {
        int i = (m >> 3) + 1, k = m & 7;
        sTwB[m] = twd(8 * i * k);
    }
    for (int m = tid; m < 448; m += 256) {
        int i = (m >> 6) + 1, jj = m & 63;
        sTwC[m] = twd(i * jj);
    }
    for (int m = tid; m < NBINS * 4; m += 256) sbin[m] = 0.0f;

    #pragma unroll 1
    for (int it = 0; it < 2; it++) {
        int p = blockIdx.x * 4 + it * 2 + pairq;     // this quarter's pair
        bool valid = (p < NRING);
        int w2 = (512 - p) & 511;
        bool self = (w2 == p);
        int col = half ? w2 : p;                     // always in [0,511] (p<=259)
        const float2* cp = g_fftT + ((size_t)b * WD + col) * HD;

        float2 v[8], w[8];
        __syncthreads();                  // tw tables ready / buf free from prev iter
        #pragma unroll
        for (int i = 0; i < 8; i++) v[i] = cp[j + 64 * i];

        dft8(v, w);                       // pass A
        #pragma unroll
        for (int u = 0; u < 8; u++) buf[quarter][PIDX(8 * j + u)] = w[u];
        __syncthreads();
        int k = j & 7;                    // pass B
        #pragma unroll
        for (int i = 0; i < 8; i++) v[i] = buf[quarter][PIDX(j + 64 * i)];
        #pragma unroll
        for (int i = 1; i < 8; i++) v[i] = cmul(v[i], sTwB[(i - 1) * 8 + k]);
        dft8(v, w);
        __syncthreads();
        {
            int base = (j & ~7) * 8 + k;
            #pragma unroll
            for (int u = 0; u < 8; u++) buf[quarter][PIDX(base + 8 * u)] = w[u];
        }
        __syncthreads();
        #pragma unroll
        for (int i = 0; i < 8; i++) v[i] = buf[quarter][PIDX(j + 64 * i)];  // pass C
        #pragma unroll
        for (int i = 1; i < 8; i++) v[i] = cmul(v[i], sTwC[(i - 1) * 64 + j]);
        dft8(v, w);
        __syncthreads();
        #pragma unroll
        for (int u = 0; u < 8; u++) buf[quarter][PIDX(j + 64 * u)] = w[u];
        __syncthreads();

        // ---- binning: threads 0-127 bin pair A, 128-255 pair B ----
        if (valid) {
            float2* FA = buf[pairq * 2];
            float2* FB = buf[pairq * 2 + 1];
            int fw = (p <= 255) ? p : p - 512;
            float fw2 = (float)(fw * fw);
            const float scale = 1.0f / (512.0f * 512.0f);
            float mulf = self ? 1.0f : 2.0f;
            int lt = tid & 127;

            #pragma unroll
            for (int q = 0; q < 4; q++) {
                int kh  = lt + 128 * q;
                int khm = (512 - kh) & 511;
                float2 P  = FA[PIDX(kh)];
                float2 Mc = FB[PIDX(khm)];
                float px = P.x * scale,  py = P.y * scale;
                float mx = Mc.x * scale, my = -Mc.y * scale;
                float f1x = 0.5f * (px + mx), f1y = 0.5f * (py + my);
                float dx  = 0.5f * (px - mx), dy  = 0.5f * (py - my);
                float f2x = dy, f2y = -dx;
                float av  = mulf * (f1x * f2x + f1y * f2y);
                float c1  = mulf * (f1x * f1x + f1y * f1y);
                float c2  = mulf * (f2x * f2x + f2y * f2y);

                int fh = (kh <= 255) ? kh : kh - 512;
                float rr = sqrtf((float)(fh * fh) + fw2);
                int r = (int)rintf(rr);           // round-half-even == jnp.round
                if (r > 256) r = 257;

                // warp-segmented sums: one atomic per contiguous equal-r run
                int rup = __shfl_up_sync(full, r, 1);
                bool head = (lane == 0) || (rup != r);
                unsigned hm = __ballot_sync(full, head);
                unsigned below = hm & (full >> (31 - lane));
                int myhead = 31 - __clz(below);
                bool tail = (lane == 31) || ((hm >> (lane + 1)) & 1u);
                int src = (myhead > 0) ? myhead - 1 : 0;

                float s0 = av, s1 = c1, s2 = c2;
                #pragma unroll
                for (int o = 1; o < 32; o <<= 1) {
                    float u0 = __shfl_up_sync(full, s0, o);
                    float u1 = __shfl_up_sync(full, s1, o);
                    float u2 = __shfl_up_sync(full, s2, o);
                    if (lane >= (unsigned)o) { s0 += u0; s1 += u1; s2 += u2; }
                }
                float b0 = __shfl_sync(full, s0, src);
                float b1 = __shfl_sync(full, s1, src);
                float b2 = __shfl_sync(full, s2, src);
                if (myhead == 0) { b0 = 0.f; b1 = 0.f; b2 = 0.f; }
                if (tail) {
                    atomicAdd(&sbin[r * 4 + 0], s0 - b0);
                    atomicAdd(&sbin[r * 4 + 2], s1 - b1);
                    atomicAdd(&sbin[r * 4 + 3], s2 - b2);
                }
                if (self) {
                    float bv = f1y * f2x - f1x * f2y;
                    atomicAdd(&sbin[r * 4 + 1], bv);   // pair blocks: +b/-b cancel
                }
            }
        }
    }
    __syncthreads();

    // ---- flush accumulated bins (4 pairs) to global ----
    float* gb = (float*)g_bins;
    for (int i = tid; i < NBINS * 4; i += 256) {
        float v2 = sbin[i];
        if (v2 != 0.0f) {
            int r = i >> 2, c = i & 3;
            atomicAdd(&gb[(r * BD + b) * 4 + c], v2);
        }
    }
    __syncthreads();

    // ---- last block finalizes: frc + mean, re-zero bins & counter ----
    if (tid == 0) {
        __threadfence();
        unsigned v = atomicAdd(&g_done, 1u);
        sIsLast = (v == (unsigned)(P2_NBLOCKS - 1));
    }
    __syncthreads();
    if (sIsLast) {
        float acc = 0.0f;
        const float4 zero4 = make_float4(0.f, 0.f, 0.f, 0.f);
        for (int i = tid; i < NBINS * BD; i += 256) {
            float4 s = __ldcg(&g_bins[i]);
            __stcg(&g_bins[i], zero4);
            int r = i / BD;
            if (r < NRING) {
                float frc = sqrtf(s.x * s.x + s.y * s.y) / (sqrtf(s.z * s.w) + 1e-8f);
                float d = 1.0f - frc;
                acc += d * d;
            }
        }
        #pragma unroll
        for (int o = 16; o > 0; o >>= 1)
            acc += __shfl_xor_sync(full, acc, o);
        __shared__ float red[8];
        if (lane == 0) red[tid >> 5] = acc;
        __syncthreads();
        if (tid < 32) {
            float v = (tid < 8) ? red[tid] : 0.0f;
            #pragma unroll
            for (int o = 4; o > 0; o >>= 1)
                v += __shfl_xor_sync(full, v, o);
            if (tid == 0) {
                out[0] = v / (float)(NRING * BD);
                atomicExch(&g_done, 0u);
            }
        }
    }
}

extern "C" void kernel_launch(void* const* d_in, const int* in_sizes, int n_in,
                              void* d_out, int out_size) {
    const float* o = (const float*)d_in[0];   // output (32,1,512,512) f32
    const float* t = (const float*)d_in[1];   // target (32,1,512,512) f32
    float* out = (float*)d_out;

    pass1_rows<<<BD * HD / 4, 256>>>(o, t);
    dim3 g2(P2_BLOCKS_X, BD);
    pass2_cols<<<g2, 256>>>(out);
}